// round 4
// baseline (speedup 1.0000x reference)
#include <cuda_runtime.h>
#include <cuda_bf16.h>

#define KDIM 4096
#define RDIM 64
#define NSLICE 16               // k-slices per block
#define KSLICE (KDIM / NSLICE)  // 256

// out[c,r] = sum_k x[xids[c*64+r], k] * A[wids[c], k, r]
// Block = one c. Threads: q = tid&15 (r-quad, r = 4q..4q+3), s = tid>>4 (k-slice).
// A loaded float4 over r (contiguous), x loaded float4 over k (per-lane stream).
__global__ void __launch_bounds__(256) lora_gather_dot_kernel(
    const float* __restrict__ x,
    const int*   __restrict__ xids,
    const int*   __restrict__ wids,
    const float* __restrict__ A,
    float*       __restrict__ out)
{
    const int c   = blockIdx.x;
    const int tid = threadIdx.x;
    const int q   = tid & 15;     // r-quad index
    const int s   = tid >> 4;     // k-slice index, 0..15
    const int r0  = q << 2;       // first r of this thread's quad

    const int wid = wids[c];

    const int t0 = xids[c * RDIM + r0 + 0];
    const int t1 = xids[c * RDIM + r0 + 1];
    const int t2 = xids[c * RDIM + r0 + 2];
    const int t3 = xids[c * RDIM + r0 + 3];

    const float* __restrict__ xr0 = x + (size_t)t0 * KDIM;
    const float* __restrict__ xr1 = x + (size_t)t1 * KDIM;
    const float* __restrict__ xr2 = x + (size_t)t2 * KDIM;
    const float* __restrict__ xr3 = x + (size_t)t3 * KDIM;

    // A[w][k][r]: element index = (w*KDIM + k)*RDIM + r
    const int k0 = s * KSLICE;
    const float* __restrict__ Ap =
        A + (size_t)wid * KDIM * RDIM + (size_t)k0 * RDIM + r0;

    float acc0 = 0.f, acc1 = 0.f, acc2 = 0.f, acc3 = 0.f;

    #pragma unroll 4
    for (int k = k0; k < k0 + KSLICE; k += 4) {
        // 8 independent 16B loads first -> MLP for L2 latency hiding
        const float4 a0 = *reinterpret_cast<const float4*>(Ap + 0 * RDIM);
        const float4 a1 = *reinterpret_cast<const float4*>(Ap + 1 * RDIM);
        const float4 a2 = *reinterpret_cast<const float4*>(Ap + 2 * RDIM);
        const float4 a3 = *reinterpret_cast<const float4*>(Ap + 3 * RDIM);
        const float4 v0 = *reinterpret_cast<const float4*>(xr0 + k);
        const float4 v1 = *reinterpret_cast<const float4*>(xr1 + k);
        const float4 v2 = *reinterpret_cast<const float4*>(xr2 + k);
        const float4 v3 = *reinterpret_cast<const float4*>(xr3 + k);
        Ap += 4 * RDIM;

        acc0 += v0.x * a0.x + v0.y * a1.x + v0.z * a2.x + v0.w * a3.x;
        acc1 += v1.x * a0.y + v1.y * a1.y + v1.z * a2.y + v1.w * a3.y;
        acc2 += v2.x * a0.z + v2.y * a1.z + v2.z * a2.z + v2.w * a3.z;
        acc3 += v3.x * a0.w + v3.y * a1.w + v3.z * a2.w + v3.w * a3.w;
    }

    __shared__ float red[NSLICE][RDIM];
    red[s][r0 + 0] = acc0;
    red[s][r0 + 1] = acc1;
    red[s][r0 + 2] = acc2;
    red[s][r0 + 3] = acc3;
    __syncthreads();

    if (tid < RDIM) {
        float sum = 0.f;
        #pragma unroll
        for (int i = 0; i < NSLICE; i++) sum += red[i][tid];
        out[c * RDIM + tid] = sum;
    }
}

extern "C" void kernel_launch(void* const* d_in, const int* in_sizes, int n_in,
                              void* d_out, int out_size)
{
    const float* x    = (const float*)d_in[0];   // [512,1,4096] f32
    const int*   xids = (const int*)  d_in[1];   // [20480] i32
    const int*   wids = (const int*)  d_in[2];   // [320] i32
    const float* A    = (const float*)d_in[3];   // [80,4096,64] f32
    float*       out  = (float*)d_out;           // [320,1,64] f32

    const int C = in_sizes[2];                   // COMBINED_BS (320)
    lora_gather_dot_kernel<<<C, 256>>>(x, xids, wids, A, out);
}

// round 5
// speedup vs baseline: 1.5289x; 1.5289x over previous
#include <cuda_runtime.h>
#include <cuda_bf16.h>

#define KDIM 4096
#define RDIM 64
#define KC 128                 // k per chunk
#define NCHUNK (KDIM / KC)     // 32
#define ASTRIDE 36             // A-smem row stride in floats (32 + 4 pad)

// out[c,r] = sum_k x[xids[c*64+r], k] * A[wids[c], k, r]
//
// Block = (c, r-half). 256 threads = 8 warps.
//   warp q (=tid>>5) owns r-quad r0 = rh*32 + 4q (4 tokens);
//   lane s (=tid&31) owns k-offsets {s, s+32, s+64, s+96} within each 128-k chunk.
// x loads: x[t_j][kc+32i+s] -> 32 consecutive floats per warp instr (1 line, coalesced).
// A staged per chunk in smem (as[k][r-window], stride 36 floats):
//   store: thread (f=tid&7, kk=tid>>3) STS.128 at (kk+32i)*36 + 4f  -> conflict-free
//   read:  LDS.128 at (s+32i)*36 + 4q                               -> conflict-free
// A gmem loads coalesced (4x128B lines/instr), prefetched one chunk ahead.
__global__ void __launch_bounds__(256, 5) lora_gather_dot_kernel(
    const float* __restrict__ x,
    const int*   __restrict__ xids,
    const int*   __restrict__ wids,
    const float* __restrict__ A,
    float*       __restrict__ out)
{
    __shared__ float as[KC * ASTRIDE];   // 18432 B

    const int c   = blockIdx.x;
    const int rh  = blockIdx.y;          // r-half 0/1
    const int tid = threadIdx.x;
    const int q   = tid >> 5;            // warp id -> r-quad
    const int s   = tid & 31;            // lane -> k sub-index
    const int f   = tid & 7;             // A-load: r-quad column
    const int kk  = tid >> 3;            // A-load: k row 0..31

    const int wid   = wids[c];
    const int rbase = rh * 32;
    const int r0    = rbase + 4 * q;

    // This warp's 4 tokens (32-bit offsets: max 512*4096 < 2^31)
    const int off0 = xids[c * RDIM + r0 + 0] * KDIM;
    const int off1 = xids[c * RDIM + r0 + 1] * KDIM;
    const int off2 = xids[c * RDIM + r0 + 2] * KDIM;
    const int off3 = xids[c * RDIM + r0 + 3] * KDIM;

    // A[w][k][r]; this block's r-window starts at rbase
    const float* __restrict__ Ab = A + (size_t)wid * KDIM * RDIM + rbase;

    // ---- prefetch + store chunk 0 ----
    float4 an0, an1, an2, an3;
    {
        const float* Ac = Ab + (size_t)kk * RDIM + 4 * f;
        an0 = *reinterpret_cast<const float4*>(Ac + 0 * 32 * RDIM);
        an1 = *reinterpret_cast<const float4*>(Ac + 1 * 32 * RDIM);
        an2 = *reinterpret_cast<const float4*>(Ac + 2 * 32 * RDIM);
        an3 = *reinterpret_cast<const float4*>(Ac + 3 * 32 * RDIM);
    }
    *reinterpret_cast<float4*>(&as[(kk +  0) * ASTRIDE + 4 * f]) = an0;
    *reinterpret_cast<float4*>(&as[(kk + 32) * ASTRIDE + 4 * f]) = an1;
    *reinterpret_cast<float4*>(&as[(kk + 64) * ASTRIDE + 4 * f]) = an2;
    *reinterpret_cast<float4*>(&as[(kk + 96) * ASTRIDE + 4 * f]) = an3;
    __syncthreads();

    float acc0 = 0.f, acc1 = 0.f, acc2 = 0.f, acc3 = 0.f;

    for (int ch = 0; ch < NCHUNK; ++ch) {
        const int kc = ch * KC;

        // prefetch next chunk's A into regs (L2 latency overlaps compute+syncs)
        if (ch + 1 < NCHUNK) {
            const float* Ac = Ab + (size_t)(kc + KC + kk) * RDIM + 4 * f;
            an0 = *reinterpret_cast<const float4*>(Ac + 0 * 32 * RDIM);
            an1 = *reinterpret_cast<const float4*>(Ac + 1 * 32 * RDIM);
            an2 = *reinterpret_cast<const float4*>(Ac + 2 * 32 * RDIM);
            an3 = *reinterpret_cast<const float4*>(Ac + 3 * 32 * RDIM);
        }

        // compute this chunk: 4 k-groups of 32
        #pragma unroll
        for (int i = 0; i < 4; ++i) {
            const int kl = s + 32 * i;
            const float4 av =
                *reinterpret_cast<const float4*>(&as[kl * ASTRIDE + 4 * q]);
            const int kx = kc + kl;
            acc0 += x[off0 + kx] * av.x;
            acc1 += x[off1 + kx] * av.y;
            acc2 += x[off2 + kx] * av.z;
            acc3 += x[off3 + kx] * av.w;
        }

        if (ch + 1 < NCHUNK) {
            __syncthreads();   // all warps done reading as
            *reinterpret_cast<float4*>(&as[(kk +  0) * ASTRIDE + 4 * f]) = an0;
            *reinterpret_cast<float4*>(&as[(kk + 32) * ASTRIDE + 4 * f]) = an1;
            *reinterpret_cast<float4*>(&as[(kk + 64) * ASTRIDE + 4 * f]) = an2;
            *reinterpret_cast<float4*>(&as[(kk + 96) * ASTRIDE + 4 * f]) = an3;
            __syncthreads();   // stores visible to all warps
        }
    }

    // reduce over the 32 lanes (k) within each warp
    #pragma unroll
    for (int off = 16; off > 0; off >>= 1) {
        acc0 += __shfl_xor_sync(0xffffffffu, acc0, off);
        acc1 += __shfl_xor_sync(0xffffffffu, acc1, off);
        acc2 += __shfl_xor_sync(0xffffffffu, acc2, off);
        acc3 += __shfl_xor_sync(0xffffffffu, acc3, off);
    }
    if (s == 0) {
        float4 o = make_float4(acc0, acc1, acc2, acc3);
        *reinterpret_cast<float4*>(&out[c * RDIM + r0]) = o;
    }
}

extern "C" void kernel_launch(void* const* d_in, const int* in_sizes, int n_in,
                              void* d_out, int out_size)
{
    const float* x    = (const float*)d_in[0];   // [512,1,4096] f32
    const int*   xids = (const int*)  d_in[1];   // [20480] i32
    const int*   wids = (const int*)  d_in[2];   // [320] i32
    const float* A    = (const float*)d_in[3];   // [80,4096,64] f32
    float*       out  = (float*)d_out;           // [320,1,64] f32

    const int C = in_sizes[2];                   // COMBINED_BS (320)
    dim3 grid(C, 2);                             // (c, r-half)
    lora_gather_dot_kernel<<<grid, 256>>>(x, xids, wids, A, out);
}